// round 3
// baseline (speedup 1.0000x reference)
#include <cuda_runtime.h>

#define B_TOT   8192
#define CAR     8
#define NAG     64
#define HID     256
#define ENC     257
#define QIN     265
#define ADIM    30
#define SROW    520
#define HPITCH  72      // floats; 288B row stride, 16B aligned

#define EG      72      // e-groups of 4 (65 real, padded to 72 = block/4)

// shared layout (in floats)
#define OFF_S   0
#define OFF_V   528
#define OFF_H   592
#define OFF_X   (OFF_H + HID * HPITCH)   // 19024
#define OFF_Y   (OFF_X + 272)            // 19296
#define SMEM_FLOATS (OFF_Y + 256)        // 19552
#define SMEM_BYTES  (SMEM_FLOATS * 4)    // 78208 B

// padded/transposed W2: [eg][k][4] so one LDG.128 fetches 4 consecutive e-columns
__device__ __align__(16) float g_W2p[EG * HID * 4];

union F2U { unsigned long long u; float2 f; };

__device__ __forceinline__ void fma2(unsigned long long& d,
                                     unsigned long long a,
                                     unsigned long long b) {
    asm("fma.rn.f32x2 %0, %1, %2, %0;" : "+l"(d) : "l"(a), "l"(b));
}

__global__ void repack_w2(const float* __restrict__ W2) {
    int idx = blockIdx.x * 256 + threadIdx.x;      // 73728 total
    int c  = idx & 3;
    int k  = (idx >> 2) & (HID - 1);
    int eg = idx >> 10;
    int e  = eg * 4 + c;
    g_W2p[idx] = (e < ENC) ? W2[k * ENC + e] : 0.0f;
}

__global__ void __launch_bounds__(288, 2) qnet_kernel(
    const float* __restrict__ s,
    const float* __restrict__ W1, const float* __restrict__ b1,
    const float* __restrict__ b2,
    const float* __restrict__ Qw1, const float* __restrict__ Qb1,
    const float* __restrict__ Qw2, const float* __restrict__ Qb2,
    float* __restrict__ out)
{
    extern __shared__ float sm[];
    float* s_sh = sm + OFF_S;
    float* v_sh = sm + OFF_V;
    float* h_sh = sm + OFF_H;
    float* x_sh = sm + OFF_X;
    float* y_sh = sm + OFF_Y;

    const int tid = threadIdx.x;
    const int b   = blockIdx.x;

    // ---- Phase 0: stage s row (row stride 2080 B = 16B multiple -> float4) ----
    {
        const float4* srow4 = reinterpret_cast<const float4*>(s + (size_t)b * SROW);
        float4* ssh4 = reinterpret_cast<float4*>(s_sh);
        for (int i = tid; i < SROW / 4; i += 288) ssh4[i] = srow4[i];
    }
    __syncthreads();

    // validity: exact fp32 compare against -1.0
    if (tid < NAG) {
        bool v = true;
        #pragma unroll
        for (int c = 0; c < CAR; c++)
            v = v && (s_sh[CAR + tid * CAR + c] != -1.0f);
        v_sh[tid] = v ? 1.0f : 0.0f;
    }

    // ---- Phase 1: h[k][n] = relu(surr[n] . W1[:,k] + b1[k]) (transposed) ----
    if (tid < HID) {
        const int k = tid;
        float w1r[CAR];
        #pragma unroll
        for (int c = 0; c < CAR; c++) w1r[c] = W1[c * HID + k];
        const float bk = b1[k];
        #pragma unroll 4
        for (int n = 0; n < NAG; n++) {
            float a = bk;
            #pragma unroll
            for (int c = 0; c < CAR; c++)
                a = fmaf(s_sh[CAR + n * CAR + c], w1r[c], a);
            h_sh[k * HPITCH + n] = fmaxf(a, 0.0f);
        }
    }
    __syncthreads();

    // ---- Phase 2: 4 e-columns x 16 agents per thread ----
    // tid = eg*4 + ag ; eg in [0,72), ag in [0,4)
    {
        const int ag = tid & 3;
        const int eg = tid >> 2;
        const int e0 = eg * 4;

        F2U acc[4][8];
        #pragma unroll
        for (int c = 0; c < 4; c++) {
            float be = (e0 + c < ENC) ? b2[e0 + c] : 0.0f;
            F2U bi; bi.f = make_float2(be, be);
            #pragma unroll
            for (int j = 0; j < 8; j++) acc[c][j].u = bi.u;
        }

        const float4* w2p = reinterpret_cast<const float4*>(g_W2p) + eg * HID;
        const float*  hag = h_sh + ag * 16;

        #pragma unroll 2
        for (int k = 0; k < HID; k++) {
            float4 w = w2p[k];                       // LDG.128: 4 e-columns
            F2U w0, w1, w2v, w3;
            w0.f  = make_float2(w.x, w.x);
            w1.f  = make_float2(w.y, w.y);
            w2v.f = make_float2(w.z, w.z);
            w3.f  = make_float2(w.w, w.w);
            const ulonglong2* hp =
                reinterpret_cast<const ulonglong2*>(hag + k * HPITCH);
            #pragma unroll
            for (int j = 0; j < 4; j++) {            // 4x LDS.128 (16 agents)
                ulonglong2 hv = hp[j];
                fma2(acc[0][2 * j].u,     hv.x, w0.u);
                fma2(acc[0][2 * j + 1].u, hv.y, w0.u);
                fma2(acc[1][2 * j].u,     hv.x, w1.u);
                fma2(acc[1][2 * j + 1].u, hv.y, w1.u);
                fma2(acc[2][2 * j].u,     hv.x, w2v.u);
                fma2(acc[2][2 * j + 1].u, hv.y, w2v.u);
                fma2(acc[3][2 * j].u,     hv.x, w3.u);
                fma2(acc[3][2 * j + 1].u, hv.y, w3.u);
            }
        }

        // relu + valid mask + agent-sum, then quad-reduce over ag via shuffle
        float sums[4];
        #pragma unroll
        for (int c = 0; c < 4; c++) {
            float sum = 0.0f;
            #pragma unroll
            for (int j = 0; j < 8; j++) {
                float lo = fmaxf(acc[c][j].f.x, 0.0f);
                float hi = fmaxf(acc[c][j].f.y, 0.0f);
                sum += lo * v_sh[ag * 16 + 2 * j] + hi * v_sh[ag * 16 + 2 * j + 1];
            }
            sums[c] = sum;
        }
        #pragma unroll
        for (int c = 0; c < 4; c++) {
            sums[c] += __shfl_xor_sync(0xffffffffu, sums[c], 1);
            sums[c] += __shfl_xor_sync(0xffffffffu, sums[c], 2);
        }
        if (ag == 0) {
            #pragma unroll
            for (int c = 0; c < 4; c++)
                if (e0 + c < ENC) x_sh[CAR + e0 + c] = sums[c];
        }
    }
    if (tid < CAR) x_sh[tid] = s_sh[tid];
    __syncthreads();

    // ---- Phase 4: y = relu(x @ Qw1 + Qb1) ----
    if (tid < HID) {
        const int j = tid;
        float a = Qb1[j];
        #pragma unroll 5
        for (int i = 0; i < QIN; i++)
            a = fmaf(x_sh[i], Qw1[i * HID + j], a);
        y_sh[j] = fmaxf(a, 0.0f);
    }
    __syncthreads();

    // ---- Phase 5: q = y @ Qw2 + Qb2 ----
    if (tid < ADIM) {
        float q = Qb2[tid];
        #pragma unroll 8
        for (int k = 0; k < HID; k++)
            q = fmaf(y_sh[k], Qw2[k * ADIM + tid], q);
        out[(size_t)b * ADIM + tid] = q;
    }
}

extern "C" void kernel_launch(void* const* d_in, const int* in_sizes, int n_in,
                              void* d_out, int out_size) {
    const float* s   = (const float*)d_in[0];
    const float* W1  = (const float*)d_in[1];
    const float* b1  = (const float*)d_in[2];
    const float* W2  = (const float*)d_in[3];
    const float* b2  = (const float*)d_in[4];
    const float* Qw1 = (const float*)d_in[5];
    const float* Qb1 = (const float*)d_in[6];
    const float* Qw2 = (const float*)d_in[7];
    const float* Qb2 = (const float*)d_in[8];
    float* out = (float*)d_out;

    repack_w2<<<288, 256>>>(W2);

    cudaFuncSetAttribute(qnet_kernel,
                         cudaFuncAttributeMaxDynamicSharedMemorySize, SMEM_BYTES);
    qnet_kernel<<<B_TOT, 288, SMEM_BYTES>>>(s, W1, b1, b2,
                                            Qw1, Qb1, Qw2, Qb2, out);
}

// round 5
// speedup vs baseline: 4.3644x; 4.3644x over previous
#include <cuda_runtime.h>

#define CAR     8
#define NAG     64
#define HID     256
#define ENC     257
#define QIN     265
#define ADIM    30
#define SROW    520
#define TB      2
#define M_ROWS  128
#define NTILES  33
#define NPAD    264
#define KSTEPS  32
#define HPITCH  260      // %32==4 -> conflict-free A-fragment LDS

#define PANEL_F 2112     // floats per k-panel in fragment order (33 tiles * 32 lanes * 2)
#define W2F_ELEMS (KSTEPS * PANEL_F)

__device__ __align__(16) float g_W2f[W2F_ELEMS];
__device__ float g_b2p[NPAD];

// shared layout (floats)
#define OFF_H   0
#define OFF_B   (OFF_H + M_ROWS * HPITCH)   // 33280
#define OFF_S   (OFF_B + 2 * PANEL_F)       // 37504
#define OFF_V   (OFF_S + TB * SROW)         // 38544
#define OFF_X   (OFF_V + M_ROWS)            // 38672
#define OFF_Y   (OFF_X + TB * 272)          // 39216
#define OFF_B2  (OFF_Y + TB * HID)          // 39728
#define SMEM_FLOATS (OFF_B2 + NPAD)         // 39992
#define SMEM_BYTES  (SMEM_FLOATS * 4)       // 159968

__device__ __forceinline__ unsigned cvt_tf32(float x) {
    unsigned r; asm("cvt.rna.tf32.f32 %0, %1;" : "=r"(r) : "f"(x)); return r;
}
__device__ __forceinline__ unsigned smem_u32(const void* p) {
    unsigned a;
    asm("{ .reg .u64 t; cvta.to.shared.u64 t, %1; cvt.u32.u64 %0, t; }" : "=r"(a) : "l"(p));
    return a;
}
__device__ __forceinline__ void mma_tf32(float* c, const unsigned* a,
                                         unsigned b0, unsigned b1) {
    asm("mma.sync.aligned.m16n8k8.row.col.f32.tf32.tf32.f32 "
        "{%0,%1,%2,%3},{%4,%5,%6,%7},{%8,%9},{%0,%1,%2,%3};"
        : "+f"(c[0]), "+f"(c[1]), "+f"(c[2]), "+f"(c[3])
        : "r"(a[0]), "r"(a[1]), "r"(a[2]), "r"(a[3]), "r"(b0), "r"(b1));
}
#define CP_ASYNC16(dst, src) \
    asm volatile("cp.async.cg.shared.global [%0],[%1],16;" :: "r"(dst), "l"(src))
#define CP_COMMIT() asm volatile("cp.async.commit_group;")

// pack W2 into per-k-step B-fragment layout: [ks][tile][lane]{b0,b1}, tf32-rna, zero-padded
__global__ void prepack(const float* __restrict__ W2, const float* __restrict__ b2) {
    int idx = blockIdx.x * 256 + threadIdx.x;
    if (idx < W2F_ELEMS) {
        int ks   = idx / PANEL_F;
        int rem  = idx % PANEL_F;
        int slot = rem & 1;
        int lane = (rem >> 1) & 31;
        int t    = rem >> 6;
        int e    = t * 8 + (lane >> 2);
        int k    = ks * 8 + (lane & 3) + slot * 4;
        float v  = (e < ENC) ? W2[k * ENC + e] : 0.0f;
        g_W2f[idx] = __uint_as_float(cvt_tf32(v));
    }
    if (idx < NPAD) g_b2p[idx] = (idx < ENC) ? b2[idx] : 0.0f;
}

__global__ void __launch_bounds__(256, 1) qnet_kernel(
    const float* __restrict__ s,
    const float* __restrict__ W1, const float* __restrict__ b1,
    const float* __restrict__ Qw1, const float* __restrict__ Qb1,
    const float* __restrict__ Qw2, const float* __restrict__ Qb2,
    float* __restrict__ out)
{
    extern __shared__ float sm[];
    float* h_sh  = sm + OFF_H;
    float* bpf   = sm + OFF_B;
    float* s_sh  = sm + OFF_S;
    float* v_sh  = sm + OFF_V;
    float* x_sh  = sm + OFF_X;
    float* y_sh  = sm + OFF_Y;
    float* b2_sh = sm + OFF_B2;

    const int tid  = threadIdx.x;
    const int lane = tid & 31;
    const int wid  = tid >> 5;
    const unsigned bpf_u32 = smem_u32(bpf);

    // kick off panel 0 immediately (independent of everything else)
    {
        const float4* src = reinterpret_cast<const float4*>(g_W2f);
        for (int i = tid; i < PANEL_F / 4; i += 256)
            CP_ASYNC16(bpf_u32 + i * 16, src + i);
        CP_COMMIT();
    }

    // ---- Phase 0: stage s rows, zero x, stage b2 ----
    {
        const float4* srow4 =
            reinterpret_cast<const float4*>(s + (size_t)blockIdx.x * TB * SROW);
        float4* ssh4 = reinterpret_cast<float4*>(s_sh);
        for (int i = tid; i < TB * SROW / 4; i += 256) ssh4[i] = srow4[i];
        for (int i = tid; i < TB * 272; i += 256) x_sh[i] = 0.0f;
        for (int i = tid; i < NPAD; i += 256) b2_sh[i] = g_b2p[i];
    }
    __syncthreads();

    // validity (exact fp32 compare)
    if (tid < M_ROWS) {
        const int bl = tid >> 6, ag = tid & 63;
        bool v = true;
        #pragma unroll
        for (int c = 0; c < CAR; c++)
            v = v && (s_sh[bl * SROW + CAR + ag * CAR + c] != -1.0f);
        v_sh[tid] = v ? 1.0f : 0.0f;
    }

    // ---- Phase 1: h[m][k] = relu(surr . W1[:,k] + b1[k]) -> tf32-rna in SMEM ----
    {
        const int k = tid;
        float w1r[CAR];
        #pragma unroll
        for (int c = 0; c < CAR; c++) w1r[c] = W1[c * HID + k];
        const float bk = b1[k];
        #pragma unroll 4
        for (int m = 0; m < M_ROWS; m++) {
            const float* sp = s_sh + (m >> 6) * SROW + CAR + (m & 63) * CAR;
            float a = bk;
            #pragma unroll
            for (int c = 0; c < CAR; c++) a = fmaf(sp[c], w1r[c], a);
            h_sh[m * HPITCH + k] = __uint_as_float(cvt_tf32(fmaxf(a, 0.0f)));
        }
    }
    if (tid < TB * CAR)   // self states (slots untouched by atomics)
        x_sh[(tid >> 3) * 272 + (tid & 7)] = s_sh[(tid >> 3) * SROW + (tid & 7)];
    __syncthreads();

    // ---- Phase 2: tf32 mma GEMM, M=128 x N=264 x K=256 ----
    const int mw = wid & 3;            // m-warp: rows mw*32 .. +31
    const int ns = wid >> 2;           // n-split
    const int ntiles = ns ? 16 : 17;
    const int tbase  = ns ? 17 : 0;

    float acc[2][17][4];
    #pragma unroll
    for (int t = 0; t < 17; t++) {
        if (t < ntiles) {
            const int e0 = (tbase + t) * 8 + (lane & 3) * 2;
            const float bb0 = b2_sh[e0], bb1 = b2_sh[e0 + 1];
            #pragma unroll
            for (int mt = 0; mt < 2; mt++) {
                acc[mt][t][0] = bb0; acc[mt][t][1] = bb1;
                acc[mt][t][2] = bb0; acc[mt][t][3] = bb1;
            }
        }
    }

    const float* habase = h_sh + (mw * 32 + (lane >> 2)) * HPITCH + (lane & 3);

    for (int ks = 0; ks < KSTEPS; ks++) {
        const int buf = ks & 1;
        if (ks + 1 < KSTEPS) {   // prefetch next panel
            const float4* src =
                reinterpret_cast<const float4*>(g_W2f + (ks + 1) * PANEL_F);
            const unsigned dst = bpf_u32 + ((buf ^ 1) * PANEL_F) * 4;
            for (int i = tid; i < PANEL_F / 4; i += 256)
                CP_ASYNC16(dst + i * 16, src + i);
            CP_COMMIT();
            asm volatile("cp.async.wait_group 1;");
        } else {
            asm volatile("cp.async.wait_group 0;");
        }
        __syncthreads();

        unsigned a[2][4];
        #pragma unroll
        for (int mt = 0; mt < 2; mt++) {
            const float* hp = habase + mt * 16 * HPITCH + ks * 8;
            a[mt][0] = __float_as_uint(hp[0]);
            a[mt][1] = __float_as_uint(hp[8 * HPITCH]);
            a[mt][2] = __float_as_uint(hp[4]);
            a[mt][3] = __float_as_uint(hp[8 * HPITCH + 4]);
        }
        const float2* bf = reinterpret_cast<const float2*>(bpf + buf * PANEL_F)
                         + tbase * 32 + lane;
        #pragma unroll
        for (int t = 0; t < 17; t++) {
            if (t < ntiles) {
                float2 b = bf[t * 32];                      // LDS.64, conflict-free
                const unsigned b0 = __float_as_uint(b.x);
                const unsigned b1 = __float_as_uint(b.y);
                mma_tf32(acc[0][t], a[0], b0, b1);
                mma_tf32(acc[1][t], a[1], b0, b1);
            }
        }
        __syncthreads();   // all reads of buf done before it is overwritten
    }

    // ---- Phase 3: relu * valid, row-reduce, accumulate into x ----
    const int bl = mw >> 1;
    #pragma unroll
    for (int t = 0; t < 17; t++) {
        if (t < ntiles) {
            float se = 0.0f, so = 0.0f;
            #pragma unroll
            for (int mt = 0; mt < 2; mt++) {
                const int mrow = mw * 32 + mt * 16 + (lane >> 2);
                const float va = v_sh[mrow], vb = v_sh[mrow + 8];
                se += fmaxf(acc[mt][t][0], 0.0f) * va + fmaxf(acc[mt][t][2], 0.0f) * vb;
                so += fmaxf(acc[mt][t][1], 0.0f) * va + fmaxf(acc[mt][t][3], 0.0f) * vb;
            }
            #pragma unroll
            for (int off = 4; off < 32; off <<= 1) {
                se += __shfl_xor_sync(0xffffffffu, se, off);
                so += __shfl_xor_sync(0xffffffffu, so, off);
            }
            if (lane < 4) {
                const int e = (tbase + t) * 8 + lane * 2;
                atomicAdd(&x_sh[bl * 272 + 8 + e], se);
                atomicAdd(&x_sh[bl * 272 + 9 + e], so);
            }
        }
    }
    __syncthreads();

    // ---- Phase 4: y = relu(x @ Qw1 + Qb1), both batch rows per thread ----
    {
        const int j = tid;
        float a0 = Qb1[j], a1 = a0;
        const float* x0 = x_sh;
        const float* x1 = x_sh + 272;
        #pragma unroll 5
        for (int i = 0; i < QIN; i++) {
            const float w = Qw1[i * HID + j];
            a0 = fmaf(x0[i], w, a0);
            a1 = fmaf(x1[i], w, a1);
        }
        y_sh[j] = fmaxf(a0, 0.0f);
        y_sh[HID + j] = fmaxf(a1, 0.0f);
    }
    __syncthreads();

    // ---- Phase 5: q = y @ Qw2 + Qb2 ----
    if (tid < TB * ADIM) {
        const int bq = tid / ADIM, aq = tid % ADIM;
        float q = Qb2[aq];
        const float* yy = y_sh + bq * HID;
        #pragma unroll 8
        for (int k = 0; k < HID; k++)
            q = fmaf(yy[k], Qw2[k * ADIM + aq], q);
        out[((size_t)blockIdx.x * TB + bq) * ADIM + aq] = q;
    }
}

extern "C" void kernel_launch(void* const* d_in, const int* in_sizes, int n_in,
                              void* d_out, int out_size) {
    const float* s   = (const float*)d_in[0];
    const float* W1  = (const float*)d_in[1];
    const float* b1  = (const float*)d_in[2];
    const float* W2  = (const float*)d_in[3];
    const float* b2  = (const float*)d_in[4];
    const float* Qw1 = (const float*)d_in[5];
    const float* Qb1 = (const float*)d_in[6];
    const float* Qw2 = (const float*)d_in[7];
    const float* Qb2 = (const float*)d_in[8];
    float* out = (float*)d_out;

    prepack<<<(W2F_ELEMS + 255) / 256, 256>>>(W2, b2);

    cudaFuncSetAttribute(qnet_kernel,
                         cudaFuncAttributeMaxDynamicSharedMemorySize, SMEM_BYTES);
    qnet_kernel<<<8192 / TB, 256, SMEM_BYTES>>>(s, W1, b1, Qw1, Qb1, Qw2, Qb2, out);
}

// round 7
// speedup vs baseline: 5.1204x; 1.1732x over previous
#include <cuda_runtime.h>

#define CAR     8
#define NAG     64
#define HID     256
#define ENC     257
#define QIN     265
#define ADIM    30
#define SROW    520
#define TB      2
#define M_ROWS  128
#define NPAD    264
#define KSTEPS  32
#define HPITCH  260      // %32==4 -> conflict-free A-fragment LDS

#define PANEL_F 2112     // floats per k-panel in fragment order (33 tiles * 32 lanes * 2)
#define W2F_ELEMS (KSTEPS * PANEL_F)

__device__ __align__(16) float g_W2f[W2F_ELEMS];
__device__ float g_b2p[NPAD];

// shared layout (floats)
#define OFF_H   0
#define OFF_S   (OFF_H + M_ROWS * HPITCH)   // 33280
#define OFF_V   (OFF_S + TB * SROW)         // 34320
#define OFF_X   (OFF_V + M_ROWS)            // 34448
#define OFF_Y   (OFF_X + TB * 272)          // 34992
#define OFF_B2  (OFF_Y + TB * HID)          // 35504
#define SMEM_FLOATS (OFF_B2 + NPAD)         // 35768
#define SMEM_BYTES  (SMEM_FLOATS * 4)       // 143072

__device__ __forceinline__ unsigned cvt_tf32(float x) {
    unsigned r; asm("cvt.rna.tf32.f32 %0, %1;" : "=r"(r) : "f"(x)); return r;
}
__device__ __forceinline__ void mma_tf32(float* c, const unsigned* a,
                                         unsigned b0, unsigned b1) {
    asm("mma.sync.aligned.m16n8k8.row.col.f32.tf32.tf32.f32 "
        "{%0,%1,%2,%3},{%4,%5,%6,%7},{%8,%9},{%0,%1,%2,%3};"
        : "+f"(c[0]), "+f"(c[1]), "+f"(c[2]), "+f"(c[3])
        : "r"(a[0]), "r"(a[1]), "r"(a[2]), "r"(a[3]), "r"(b0), "r"(b1));
}

// pack W2 into per-k-step B-fragment layout: [ks][tile][lane]{b0,b1}, tf32-rna, zero-padded
__global__ void prepack(const float* __restrict__ W2, const float* __restrict__ b2) {
    int idx = blockIdx.x * 256 + threadIdx.x;
    if (idx < W2F_ELEMS) {
        int ks   = idx / PANEL_F;
        int rem  = idx % PANEL_F;
        int slot = rem & 1;
        int lane = (rem >> 1) & 31;
        int t    = rem >> 6;
        int e    = t * 8 + (lane >> 2);
        int k    = ks * 8 + (lane & 3) + slot * 4;
        float v  = (e < ENC) ? W2[k * ENC + e] : 0.0f;
        g_W2f[idx] = __uint_as_float(cvt_tf32(v));
    }
    if (idx < NPAD) g_b2p[idx] = (idx < ENC) ? b2[idx] : 0.0f;
}

__global__ void __launch_bounds__(512, 1) qnet_kernel(
    const float* __restrict__ s,
    const float* __restrict__ W1, const float* __restrict__ b1,
    const float* __restrict__ Qw1, const float* __restrict__ Qb1,
    const float* __restrict__ Qw2, const float* __restrict__ Qb2,
    float* __restrict__ out)
{
    extern __shared__ float sm[];
    float* h_sh  = sm + OFF_H;
    float* s_sh  = sm + OFF_S;
    float* v_sh  = sm + OFF_V;
    float* x_sh  = sm + OFF_X;
    float* y_sh  = sm + OFF_Y;
    float* b2_sh = sm + OFF_B2;

    const int tid  = threadIdx.x;
    const int lane = tid & 31;
    const int wid  = tid >> 5;

    // ---- Phase 0: stage s rows, zero x (ALL TB*272 = 544 slots!), stage b2 ----
    {
        const float4* srow4 =
            reinterpret_cast<const float4*>(s + (size_t)blockIdx.x * TB * SROW);
        float4* ssh4 = reinterpret_cast<float4*>(s_sh);
        for (int i = tid; i < TB * SROW / 4; i += 512) ssh4[i] = srow4[i];
        for (int i = tid; i < TB * 272; i += 512) x_sh[i] = 0.0f;
        if (tid < NPAD) b2_sh[tid] = g_b2p[tid];
    }
    __syncthreads();

    // validity (exact fp32 compare)
    if (tid < M_ROWS) {
        const int bl = tid >> 6, ag = tid & 63;
        bool v = true;
        #pragma unroll
        for (int c = 0; c < CAR; c++)
            v = v && (s_sh[bl * SROW + CAR + ag * CAR + c] != -1.0f);
        v_sh[tid] = v ? 1.0f : 0.0f;
    }

    // ---- Phase 1: h[m][k] = relu(surr . W1[:,k] + b1[k]) -> tf32-rna in SMEM ----
    // 512 threads: k = tid&255, each handles 64 of the 128 rows
    {
        const int k    = tid & 255;
        const int half = tid >> 8;
        float w1r[CAR];
        #pragma unroll
        for (int c = 0; c < CAR; c++) w1r[c] = W1[c * HID + k];
        const float bk = b1[k];
        #pragma unroll 4
        for (int mm = 0; mm < 64; mm++) {
            const int m = half * 64 + mm;
            const float* sp = s_sh + (m >> 6) * SROW + CAR + (m & 63) * CAR;
            float a = bk;
            #pragma unroll
            for (int c = 0; c < CAR; c++) a = fmaf(sp[c], w1r[c], a);
            h_sh[m * HPITCH + k] = __uint_as_float(cvt_tf32(fmaxf(a, 0.0f)));
        }
    }
    if (tid < TB * CAR)   // self states (slots untouched by atomics)
        x_sh[(tid >> 3) * 272 + (tid & 7)] = s_sh[(tid >> 3) * SROW + (tid & 7)];
    __syncthreads();
    // ================= no __syncthreads inside the GEMM mainloop =================

    // ---- Phase 2: tf32 mma GEMM, M=128 x N=264 x K=256 ----
    // 16 warps: 4 m-warps x 4 n-splits; tiles per split: 9,8,8,8
    const int mw = wid & 3;
    const int ns = wid >> 2;
    const int ntiles = ns ? 8 : 9;
    const int tbase  = ns ? (1 + ns * 8) : 0;

    float acc[2][9][4];
    #pragma unroll
    for (int t = 0; t < 9; t++) {
        if (t < ntiles) {
            const int e0 = (tbase + t) * 8 + (lane & 3) * 2;
            const float bb0 = b2_sh[e0], bb1 = b2_sh[e0 + 1];
            #pragma unroll
            for (int mt = 0; mt < 2; mt++) {
                acc[mt][t][0] = bb0; acc[mt][t][1] = bb1;
                acc[mt][t][2] = bb0; acc[mt][t][3] = bb1;
            }
        }
    }

    const float* habase = h_sh + (mw * 32 + (lane >> 2)) * HPITCH + (lane & 3);
    // B fragments straight from global (L2-resident), register double-buffered
    const float2* bgl = reinterpret_cast<const float2*>(g_W2f) + tbase * 32 + lane;

    float2 bnext[9];
    #pragma unroll
    for (int t = 0; t < 9; t++)
        if (t < ntiles) bnext[t] = bgl[t * 32];

    #pragma unroll 2
    for (int ks = 0; ks < KSTEPS; ks++) {
        float2 bcur[9];
        #pragma unroll
        for (int t = 0; t < 9; t++)
            if (t < ntiles) bcur[t] = bnext[t];

        if (ks + 1 < KSTEPS) {
            const float2* bn = bgl + (ks + 1) * (PANEL_F / 2);
            #pragma unroll
            for (int t = 0; t < 9; t++)
                if (t < ntiles) bnext[t] = bn[t * 32];
        }

        unsigned a[2][4];
        #pragma unroll
        for (int mt = 0; mt < 2; mt++) {
            const float* hp = habase + mt * 16 * HPITCH + ks * 8;
            a[mt][0] = __float_as_uint(hp[0]);
            a[mt][1] = __float_as_uint(hp[8 * HPITCH]);
            a[mt][2] = __float_as_uint(hp[4]);
            a[mt][3] = __float_as_uint(hp[8 * HPITCH + 4]);
        }
        #pragma unroll
        for (int t = 0; t < 9; t++) {
            if (t < ntiles) {
                const unsigned b0 = __float_as_uint(bcur[t].x);
                const unsigned b1 = __float_as_uint(bcur[t].y);
                mma_tf32(acc[0][t], a[0], b0, b1);
                mma_tf32(acc[1][t], a[1], b0, b1);
            }
        }
    }

    // ---- Phase 3: relu * valid, row-reduce, accumulate into x ----
    const int bl = mw >> 1;
    #pragma unroll
    for (int t = 0; t < 9; t++) {
        if (t < ntiles) {
            float se = 0.0f, so = 0.0f;
            #pragma unroll
            for (int mt = 0; mt < 2; mt++) {
                const int mrow = mw * 32 + mt * 16 + (lane >> 2);
                const float va = v_sh[mrow], vb = v_sh[mrow + 8];
                se += fmaxf(acc[mt][t][0], 0.0f) * va + fmaxf(acc[mt][t][2], 0.0f) * vb;
                so += fmaxf(acc[mt][t][1], 0.0f) * va + fmaxf(acc[mt][t][3], 0.0f) * vb;
            }
            #pragma unroll
            for (int off = 4; off < 32; off <<= 1) {
                se += __shfl_xor_sync(0xffffffffu, se, off);
                so += __shfl_xor_sync(0xffffffffu, so, off);
            }
            if (lane < 4) {
                const int e = (tbase + t) * 8 + lane * 2;
                atomicAdd(&x_sh[bl * 272 + 8 + e], se);
                atomicAdd(&x_sh[bl * 272 + 9 + e], so);
            }
        }
    }
    __syncthreads();

    // ---- Phase 4: y = relu(x @ Qw1 + Qb1), 512 threads: one (row, j) each ----
    {
        const int j  = tid & 255;
        const int bq = tid >> 8;
        float a = Qb1[j];
        const float* xx = x_sh + bq * 272;
        #pragma unroll 5
        for (int i = 0; i < QIN; i++)
            a = fmaf(xx[i], Qw1[i * HID + j], a);
        y_sh[bq * HID + j] = fmaxf(a, 0.0f);
    }
    __syncthreads();

    // ---- Phase 5: q = y @ Qw2 + Qb2 ----
    if (tid < TB * ADIM) {
        const int bq = tid / ADIM, aq = tid % ADIM;
        float q = Qb2[aq];
        const float* yy = y_sh + bq * HID;
        #pragma unroll 8
        for (int k = 0; k < HID; k++)
            q = fmaf(yy[k], Qw2[k * ADIM + aq], q);
        out[((size_t)blockIdx.x * TB + bq) * ADIM + aq] = q;
    }
}

extern "C" void kernel_launch(void* const* d_in, const int* in_sizes, int n_in,
                              void* d_out, int out_size) {
    const float* s   = (const float*)d_in[0];
    const float* W1  = (const float*)d_in[1];
    const float* b1  = (const float*)d_in[2];
    const float* W2  = (const float*)d_in[3];
    const float* b2  = (const float*)d_in[4];
    const float* Qw1 = (const float*)d_in[5];
    const float* Qb1 = (const float*)d_in[6];
    const float* Qw2 = (const float*)d_in[7];
    const float* Qb2 = (const float*)d_in[8];
    float* out = (float*)d_out;

    prepack<<<(W2F_ELEMS + 255) / 256, 256>>>(W2, b2);

    cudaFuncSetAttribute(qnet_kernel,
                         cudaFuncAttributeMaxDynamicSharedMemorySize, SMEM_BYTES);
    qnet_kernel<<<8192 / TB, 512, SMEM_BYTES>>>(s, W1, b1, Qw1, Qb1, Qw2, Qb2, out);
}

// round 8
// speedup vs baseline: 6.6308x; 1.2950x over previous
#include <cuda_runtime.h>

#define CAR     8
#define NAG     64
#define HID     256
#define ENC     257
#define QIN     265
#define ADIM    30
#define SROW    520
#define M_ROWS  64
#define NPAD    264
#define KSTEPS  32
#define KPAIRS  16
#define NTILES  33
#define HPITCH  264      // mod 32 == 8 -> conflict-free float2 A-frag LDS

// B layout: [pair][tile][lane]{b0_even,b1_even,b0_odd,b1_odd}
#define W2F_ELEMS (KPAIRS * NTILES * 32 * 4)   // 67584

__device__ __align__(16) float g_W2f[W2F_ELEMS];
__device__ float g_b2p[NPAD];
__device__ __align__(16) float g_x[8192 * 272];

// kernel1 shared (floats)
#define OFF_H   0
#define OFF_S   (OFF_H + M_ROWS * HPITCH)   // 16896
#define OFF_V   (OFF_S + SROW)              // 17416
#define OFF_X   (OFF_V + M_ROWS)            // 17480
#define OFF_B2  (OFF_X + 272)               // 17752
#define SM1_FLOATS (OFF_B2 + NPAD)          // 18016
#define SM1_BYTES  (SM1_FLOATS * 4)         // 72064

// kernel2 shared
#define SM2_BYTES ((64 * 272 + 64 * 256) * 4)  // 135168

__device__ __forceinline__ unsigned cvt_tf32(float x) {
    unsigned r; asm("cvt.rna.tf32.f32 %0, %1;" : "=r"(r) : "f"(x)); return r;
}
__device__ __forceinline__ void mma_tf32(float* c, const unsigned* a,
                                         unsigned b0, unsigned b1) {
    asm("mma.sync.aligned.m16n8k8.row.col.f32.tf32.tf32.f32 "
        "{%0,%1,%2,%3},{%4,%5,%6,%7},{%8,%9},{%0,%1,%2,%3};"
        : "+f"(c[0]), "+f"(c[1]), "+f"(c[2]), "+f"(c[3])
        : "r"(a[0]), "r"(a[1]), "r"(a[2]), "r"(a[3]), "r"(b0), "r"(b1));
}

// pack W2 tf32-rna into paired-k fragment layout (B-frag mapping verified in R4/R6)
__global__ void prepack(const float* __restrict__ W2, const float* __restrict__ b2) {
    int idx = blockIdx.x * 256 + threadIdx.x;
    if (idx < W2F_ELEMS) {
        int q    = idx & 3;
        int rem  = idx >> 2;
        int lane = rem & 31;
        int rem2 = rem >> 5;
        int t    = rem2 % NTILES;
        int p    = rem2 / NTILES;
        int e    = t * 8 + (lane >> 2);
        int k    = (2 * p + (q >> 1)) * 8 + (lane & 3) + (q & 1) * 4;
        float v  = (e < ENC) ? W2[k * ENC + e] : 0.0f;
        g_W2f[idx] = __uint_as_float(cvt_tf32(v));
    }
    if (idx < NPAD) g_b2p[idx] = (idx < ENC) ? b2[idx] : 0.0f;
}

// ================= kernel 1: encoder (phases 0-3) -> g_x =================
__global__ void __launch_bounds__(256, 2) enc_kernel(
    const float* __restrict__ s,
    const float* __restrict__ W1, const float* __restrict__ b1)
{
    extern __shared__ float sm[];
    float* h_sh  = sm + OFF_H;
    float* s_sh  = sm + OFF_S;
    float* v_sh  = sm + OFF_V;
    float* x_sh  = sm + OFF_X;
    float* b2_sh = sm + OFF_B2;

    const int tid  = threadIdx.x;
    const int lane = tid & 31;
    const int wid  = tid >> 5;
    const int bid  = blockIdx.x;

    // ---- stage s row, zero x, stage b2 ----
    {
        const float4* srow4 = reinterpret_cast<const float4*>(s + (size_t)bid * SROW);
        float4* ssh4 = reinterpret_cast<float4*>(s_sh);
        if (tid < SROW / 4) ssh4[tid] = srow4[tid];
        for (int i = tid; i < 272; i += 256) x_sh[i] = 0.0f;
        for (int i = tid; i < NPAD; i += 256) b2_sh[i] = g_b2p[i];
    }
    __syncthreads();

    if (tid < NAG) {        // validity: exact fp32 compare
        bool v = true;
        #pragma unroll
        for (int c = 0; c < CAR; c++)
            v = v && (s_sh[CAR + tid * CAR + c] != -1.0f);
        v_sh[tid] = v ? 1.0f : 0.0f;
    }

    // ---- phase 1: h (tf32, k-permuted within groups of 8: pos=2*(k&3)+((k>>2)&1)) ----
    {
        const int k = tid;
        float w1r[CAR];
        #pragma unroll
        for (int c = 0; c < CAR; c++) w1r[c] = W1[c * HID + k];
        const float bk = b1[k];
        const int pos = (k & ~7) + 2 * (k & 3) + ((k >> 2) & 1);
        #pragma unroll 4
        for (int m = 0; m < M_ROWS; m++) {
            const float* sp = s_sh + CAR + m * CAR;
            float a = bk;
            #pragma unroll
            for (int c = 0; c < CAR; c++) a = fmaf(sp[c], w1r[c], a);
            h_sh[m * HPITCH + pos] = __uint_as_float(cvt_tf32(fmaxf(a, 0.0f)));
        }
    }
    if (tid < CAR) x_sh[tid] = s_sh[tid];   // self states
    __syncthreads();
    // ============ no __syncthreads inside the GEMM mainloop ============

    // ---- phase 2: tf32 mma, M=64 x N=264 x K=256; 8 warps = 2 mw x 4 ns ----
    const int mw = wid & 1;
    const int ns = wid >> 1;
    const int ntiles = ns ? 8 : 9;
    const int tbase  = ns ? (1 + ns * 8) : 0;

    float acc[2][9][4];
    #pragma unroll
    for (int t = 0; t < 9; t++) {
        if (t < ntiles) {
            const int e0 = (tbase + t) * 8 + (lane & 3) * 2;
            const float bb0 = b2_sh[e0], bb1 = b2_sh[e0 + 1];
            #pragma unroll
            for (int mt = 0; mt < 2; mt++) {
                acc[mt][t][0] = bb0; acc[mt][t][1] = bb1;
                acc[mt][t][2] = bb0; acc[mt][t][3] = bb1;
            }
        }
    }

    const float* habase = h_sh + (mw * 32 + (lane >> 2)) * HPITCH + (lane & 3) * 2;
    const float4* bgl4  = reinterpret_cast<const float4*>(g_W2f) + lane;

    for (int p = 0; p < KPAIRS; p++) {
        unsigned ae[2][4], ao[2][4];
        #pragma unroll
        for (int mt = 0; mt < 2; mt++) {
            const float* hp = habase + mt * 16 * HPITCH + p * 16;
            float2 lo  = *reinterpret_cast<const float2*>(hp);
            float2 hi  = *reinterpret_cast<const float2*>(hp + 8 * HPITCH);
            float2 lo2 = *reinterpret_cast<const float2*>(hp + 8);
            float2 hi2 = *reinterpret_cast<const float2*>(hp + 8 * HPITCH + 8);
            ae[mt][0] = __float_as_uint(lo.x);  ae[mt][1] = __float_as_uint(hi.x);
            ae[mt][2] = __float_as_uint(lo.y);  ae[mt][3] = __float_as_uint(hi.y);
            ao[mt][0] = __float_as_uint(lo2.x); ao[mt][1] = __float_as_uint(hi2.x);
            ao[mt][2] = __float_as_uint(lo2.y); ao[mt][3] = __float_as_uint(hi2.y);
        }
        #pragma unroll
        for (int t = 0; t < 9; t++) {
            if (t < ntiles) {
                float4 b = bgl4[(p * NTILES + tbase + t) * 32];   // LDG.128 = 2 k-steps
                const unsigned b0 = __float_as_uint(b.x), b1 = __float_as_uint(b.y);
                const unsigned b2v = __float_as_uint(b.z), b3 = __float_as_uint(b.w);
                mma_tf32(acc[0][t], ae[0], b0, b1);
                mma_tf32(acc[1][t], ae[1], b0, b1);
                mma_tf32(acc[0][t], ao[0], b2v, b3);
                mma_tf32(acc[1][t], ao[1], b2v, b3);
            }
        }
    }

    // ---- phase 3: relu * valid, reduce rows, accumulate into x ----
    #pragma unroll
    for (int t = 0; t < 9; t++) {
        if (t < ntiles) {
            float se = 0.0f, so = 0.0f;
            #pragma unroll
            for (int mt = 0; mt < 2; mt++) {
                const int mrow = mw * 32 + mt * 16 + (lane >> 2);
                const float va = v_sh[mrow], vb = v_sh[mrow + 8];
                se += fmaxf(acc[mt][t][0], 0.0f) * va + fmaxf(acc[mt][t][2], 0.0f) * vb;
                so += fmaxf(acc[mt][t][1], 0.0f) * va + fmaxf(acc[mt][t][3], 0.0f) * vb;
            }
            #pragma unroll
            for (int off = 4; off < 32; off <<= 1) {
                se += __shfl_xor_sync(0xffffffffu, se, off);
                so += __shfl_xor_sync(0xffffffffu, so, off);
            }
            if (lane < 4) {
                const int e = (tbase + t) * 8 + lane * 2;
                atomicAdd(&x_sh[8 + e], se);
                atomicAdd(&x_sh[9 + e], so);
            }
        }
    }
    __syncthreads();

    for (int i = tid; i < 272; i += 256) g_x[(size_t)bid * 272 + i] = x_sh[i];
}

// ================= kernel 2: Q-head, 64 rows per CTA =================
__global__ void __launch_bounds__(256, 1) qhead_kernel(
    const float* __restrict__ Qw1, const float* __restrict__ Qb1,
    const float* __restrict__ Qw2, const float* __restrict__ Qb2,
    float* __restrict__ out)
{
    extern __shared__ float sm[];
    float* x_sh = sm;                  // 64 x 272
    float* y_sh = sm + 64 * 272;       // 64 x 256

    const int tid = threadIdx.x;
    const int bid = blockIdx.x;

    {   // stage 64 x-rows
        const float4* src = reinterpret_cast<const float4*>(g_x + (size_t)bid * 64 * 272);
        float4* dst = reinterpret_cast<float4*>(x_sh);
        for (int i = tid; i < 64 * 272 / 4; i += 256) dst[i] = src[i];
    }
    __syncthreads();

    // y = relu(x @ Qw1 + Qb1): 4 passes of 16 rows, thread owns column j
    const int j = tid;
    const float bj = Qb1[j];
    for (int pass = 0; pass < 4; pass++) {
        const int rbase = pass * 16;
        float acc[16];
        #pragma unroll
        for (int rr = 0; rr < 16; rr++) acc[rr] = bj;
        for (int i = 0; i < QIN; i++) {
            const float w = Qw1[i * HID + j];
            const float* xp = x_sh + rbase * 272 + i;
            #pragma unroll
            for (int rr = 0; rr < 16; rr++)
                acc[rr] = fmaf(xp[rr * 272], w, acc[rr]);
        }
        #pragma unroll
        for (int rr = 0; rr < 16; rr++)
            y_sh[(rbase + rr) * 256 + j] = fmaxf(acc[rr], 0.0f);
    }
    __syncthreads();

    // q = y @ Qw2 + Qb2
    for (int idx = tid; idx < 64 * ADIM; idx += 256) {
        const int r = idx / ADIM, aq = idx % ADIM;
        float q = Qb2[aq];
        const float* yy = y_sh + r * 256;
        #pragma unroll 8
        for (int k = 0; k < HID; k++)
            q = fmaf(yy[k], Qw2[k * ADIM + aq], q);
        out[((size_t)bid * 64 + r) * ADIM + aq] = q;
    }
}

extern "C" void kernel_launch(void* const* d_in, const int* in_sizes, int n_in,
                              void* d_out, int out_size) {
    const float* s   = (const float*)d_in[0];
    const float* W1  = (const float*)d_in[1];
    const float* b1  = (const float*)d_in[2];
    const float* W2  = (const float*)d_in[3];
    const float* b2  = (const float*)d_in[4];
    const float* Qw1 = (const float*)d_in[5];
    const float* Qb1 = (const float*)d_in[6];
    const float* Qw2 = (const float*)d_in[7];
    const float* Qb2 = (const float*)d_in[8];
    float* out = (float*)d_out;

    prepack<<<(W2F_ELEMS + 255) / 256, 256>>>(W2, b2);

    cudaFuncSetAttribute(enc_kernel,
                         cudaFuncAttributeMaxDynamicSharedMemorySize, SM1_BYTES);
    enc_kernel<<<8192, 256, SM1_BYTES>>>(s, W1, b1);

    cudaFuncSetAttribute(qhead_kernel,
                         cudaFuncAttributeMaxDynamicSharedMemorySize, SM2_BYTES);
    qhead_kernel<<<128, 256, SM2_BYTES>>>(Qw1, Qb1, Qw2, Qb2, out);
}